// round 1
// baseline (speedup 1.0000x reference)
#include <cuda_runtime.h>

// Problem constants (fixed by the dataset)
#define B_   8
#define S_   4096
#define D_   64
#define BQ   64     // q rows per CTA
#define BK   64     // k cols per tile
#define NT   256    // threads per CTA
#define PSTR 68     // padded stride for P^T staging (breaks bank conflicts)

// d_out layout: [output (B*S*D floats)][attention (B*S*S floats)]

__global__ __launch_bounds__(NT, 2) void attn_fused(
    const float* __restrict__ Q, const float* __restrict__ K,
    const float* __restrict__ V, float* __restrict__ Out,
    float* __restrict__ Attn)
{
    // smA: pass1 = Q^T [d][q] (stride BQ) ; pass2 = V tile [k][d] row-major
    // smB: pass1 = K^T [d][k] (stride BK) ; pass2 = P^T [k][q] (stride PSTR)
    __shared__ float smA[BQ * D_];
    __shared__ float smB[BK * PSTR];
    __shared__ float m_row[BQ];
    __shared__ float il_row[BQ];

    const int tid = threadIdx.x;
    const int b   = blockIdx.y;
    const int bx  = blockIdx.x;
    // pair heavy (large qt) with light CTAs for SM load balance
    const int qt  = (bx & 1) ? (63 - (bx >> 1)) : (bx >> 1);

    const int qg = tid >> 4;      // 0..15
    const int kg = tid & 15;      // 0..15
    const int q0 = qg * 4;
    const int k0 = kg * 4;

    const float NEGINF = __int_as_float(0xff800000);

    // ---------------- zero-fill upper-triangle tiles of attention ----------------
    {
        const int zstart = (qt + 1) * BK;
        const int zw4 = (S_ - zstart) >> 2;     // float4s per row to zero
        if (zw4 > 0) {
            const float4 z4 = make_float4(0.f, 0.f, 0.f, 0.f);
            const int total = BQ * zw4;
            for (int idx = tid; idx < total; idx += NT) {
                const int r = idx / zw4;
                const int c = idx - r * zw4;
                float4* dst = (float4*)&Attn[((size_t)(b * S_ + qt * BQ + r)) * S_ + zstart];
                dst[c] = z4;
            }
        }
    }

    // ---------------- load Q tile transposed into smA[d][q] ----------------
    {
        const int c  = tid & 15;   // d-chunk of 4
        const int r0 = tid >> 4;   // q row
        #pragma unroll
        for (int it = 0; it < 4; it++) {
            const int r = r0 + it * 16;
            float4 v = *(const float4*)&Q[((size_t)(b * S_ + qt * BQ + r)) * D_ + c * 4];
            smA[(c * 4 + 0) * BQ + r] = v.x;
            smA[(c * 4 + 1) * BQ + r] = v.y;
            smA[(c * 4 + 2) * BQ + r] = v.z;
            smA[(c * 4 + 3) * BQ + r] = v.w;
        }
    }

    float m_i[4], l_i[4];
    #pragma unroll
    for (int i = 0; i < 4; i++) { m_i[i] = -1e30f; l_i[i] = 0.f; }

    // =============================== PASS 1 ===============================
    // scores -> Attn (raw, lower triangle), online row max / sum(exp)
    for (int kt = 0; kt <= qt; kt++) {
        __syncthreads();
        // load K tile transposed into smB[d][k]
        {
            const int c  = tid & 15;
            const int r0 = tid >> 4;
            #pragma unroll
            for (int it = 0; it < 4; it++) {
                const int r = r0 + it * 16;
                float4 v = *(const float4*)&K[((size_t)(b * S_ + kt * BK + r)) * D_ + c * 4];
                smB[(c * 4 + 0) * BK + r] = v.x;
                smB[(c * 4 + 1) * BK + r] = v.y;
                smB[(c * 4 + 2) * BK + r] = v.z;
                smB[(c * 4 + 3) * BK + r] = v.w;
            }
        }
        __syncthreads();

        float acc[4][4];
        #pragma unroll
        for (int i = 0; i < 4; i++)
            #pragma unroll
            for (int j = 0; j < 4; j++) acc[i][j] = 0.f;

        #pragma unroll 16
        for (int d = 0; d < D_; d++) {
            float4 qv = *(const float4*)&smA[d * BQ + q0];
            float4 kv = *(const float4*)&smB[d * BK + k0];
            float qa[4] = {qv.x, qv.y, qv.z, qv.w};
            float ka[4] = {kv.x, kv.y, kv.z, kv.w};
            #pragma unroll
            for (int i = 0; i < 4; i++)
                #pragma unroll
                for (int j = 0; j < 4; j++)
                    acc[i][j] = fmaf(qa[i], ka[j], acc[i][j]);
        }

        const int qb = qt * BQ + q0;
        const int kb = kt * BK + k0;
        #pragma unroll
        for (int i = 0; i < 4; i++) {
            float s[4];
            #pragma unroll
            for (int j = 0; j < 4; j++) {
                float v = acc[i][j] * 0.125f;   // 1/sqrt(64)
                if (kt == qt && (kb + j) > (qb + i)) v = NEGINF;
                s[j] = v;
            }
            const float tmax = fmaxf(fmaxf(s[0], s[1]), fmaxf(s[2], s[3]));
            const float mn = fmaxf(m_i[i], tmax);
            const float add = __expf(s[0] - mn) + __expf(s[1] - mn)
                            + __expf(s[2] - mn) + __expf(s[3] - mn);
            l_i[i] = l_i[i] * __expf(m_i[i] - mn) + add;
            m_i[i] = mn;
            *(float4*)&Attn[((size_t)(b * S_ + qb + i)) * S_ + kb] =
                make_float4(s[0], s[1], s[2], s[3]);
        }
    }

    // reduce (m, l) across the 16 lanes (kg) sharing each q row
    #pragma unroll
    for (int off = 8; off >= 1; off >>= 1) {
        #pragma unroll
        for (int i = 0; i < 4; i++) {
            const float m2 = __shfl_xor_sync(0xffffffffu, m_i[i], off);
            const float l2 = __shfl_xor_sync(0xffffffffu, l_i[i], off);
            const float mn = fmaxf(m_i[i], m2);
            l_i[i] = l_i[i] * __expf(m_i[i] - mn) + l2 * __expf(m2 - mn);
            m_i[i] = mn;
        }
    }
    if (kg == 0) {
        #pragma unroll
        for (int i = 0; i < 4; i++) {
            m_row[q0 + i]  = m_i[i];
            il_row[q0 + i] = 1.0f / l_i[i];
        }
    }
    __syncthreads();

    float mreg[4], ilreg[4];
    #pragma unroll
    for (int i = 0; i < 4; i++) {
        mreg[i]  = m_row[q0 + i];
        ilreg[i] = il_row[q0 + i];
    }

    float acc_o[4][4];
    #pragma unroll
    for (int i = 0; i < 4; i++)
        #pragma unroll
        for (int j = 0; j < 4; j++) acc_o[i][j] = 0.f;

    const int d0 = k0;   // reuse kg as d-group in the AV GEMM

    // =============================== PASS 2 ===============================
    // read raw scores back, normalize -> Attn, accumulate O += P @ V
    for (int kt = 0; kt <= qt; kt++) {
        __syncthreads();
        // load V tile [k][d] row-major into smA
        {
            const float4* gv = (const float4*)&V[((size_t)(b * S_ + kt * BK)) * D_];
            float4* sv = (float4*)smA;
            for (int idx = tid; idx < (BK * D_) / 4; idx += NT)
                sv[idx] = gv[idx];
        }

        const int qb = qt * BQ + q0;
        const int kb = kt * BK + k0;
        float p[4][4];
        #pragma unroll
        for (int i = 0; i < 4; i++) {
            float4 sv4 = *(const float4*)&Attn[((size_t)(b * S_ + qb + i)) * S_ + kb];
            float sarr[4] = {sv4.x, sv4.y, sv4.z, sv4.w};
            #pragma unroll
            for (int j = 0; j < 4; j++)
                p[i][j] = __expf(sarr[j] - mreg[i]) * ilreg[i];   // -inf -> exactly 0
            *(float4*)&Attn[((size_t)(b * S_ + qb + i)) * S_ + kb] =
                make_float4(p[i][0], p[i][1], p[i][2], p[i][3]);
        }
        // stage P^T[k][q] (stride PSTR) for the AV GEMM
        #pragma unroll
        for (int j = 0; j < 4; j++)
            *(float4*)&smB[(k0 + j) * PSTR + q0] =
                make_float4(p[0][j], p[1][j], p[2][j], p[3][j]);
        __syncthreads();

        #pragma unroll 16
        for (int kk = 0; kk < BK; kk++) {
            float4 pv = *(const float4*)&smB[kk * PSTR + q0];
            float4 vv = *(const float4*)&smA[kk * D_ + d0];
            float pa[4] = {pv.x, pv.y, pv.z, pv.w};
            float va[4] = {vv.x, vv.y, vv.z, vv.w};
            #pragma unroll
            for (int i = 0; i < 4; i++)
                #pragma unroll
                for (int j = 0; j < 4; j++)
                    acc_o[i][j] = fmaf(pa[i], va[j], acc_o[i][j]);
        }
    }

    // ---------------- write O ----------------
    {
        const int qb = qt * BQ + q0;
        #pragma unroll
        for (int i = 0; i < 4; i++)
            *(float4*)&Out[((size_t)(b * S_ + qb + i)) * D_ + d0] =
                make_float4(acc_o[i][0], acc_o[i][1], acc_o[i][2], acc_o[i][3]);
    }
}

extern "C" void kernel_launch(void* const* d_in, const int* in_sizes, int n_in,
                              void* d_out, int out_size) {
    (void)in_sizes; (void)n_in; (void)out_size;
    const float* Q = (const float*)d_in[0];
    const float* K = (const float*)d_in[1];
    const float* V = (const float*)d_in[2];
    // mask input (d_in[3]) is the static causal flag == 1; causal path hardcoded.
    float* Out  = (float*)d_out;
    float* Attn = Out + (size_t)B_ * S_ * D_;

    dim3 grid(S_ / BQ, B_);
    attn_fused<<<grid, NT>>>(Q, K, V, Out, Attn);
}

// round 3
// speedup vs baseline: 1.3224x; 1.3224x over previous
#include <cuda_runtime.h>
#include <cuda_bf16.h>
#include <cstdint>

#define B_   8
#define S_   4096
#define D_   64
#define BQ   64
#define BK   64
#define NT   128
#define KSTR 72                      // bf16 elems per smem row (144B: conflict-free ldmatrix)
#define L2E  1.4426950408889634f

// Pre-split operands (bf16 hi/lo). 16 MB of static device scratch (allowed).
__device__ __nv_bfloat16 g_Khi[B_*S_*D_];
__device__ __nv_bfloat16 g_Klo[B_*S_*D_];
__device__ __nv_bfloat16 g_Vthi[B_*D_*S_];   // V transposed: [b][d][s]
__device__ __nv_bfloat16 g_Vtlo[B_*D_*S_];

__global__ void preconvert(const float* __restrict__ K, const float* __restrict__ V) {
    int idx = blockIdx.x * blockDim.x + threadIdx.x;
    if (idx >= B_*S_*D_) return;
    // K path: same layout
    float k = K[idx];
    __nv_bfloat16 kh = __float2bfloat16(k);
    g_Khi[idx] = kh;
    g_Klo[idx] = __float2bfloat16(k - __bfloat162float(kh));
    // V path: idx = (b, d, s) so writes are coalesced
    int b = idx >> 18;               // 64*4096 = 2^18
    int rem = idx & ((1 << 18) - 1);
    int d = rem >> 12;
    int s = rem & (S_ - 1);
    float v = V[(size_t)b*S_*D_ + (size_t)s*D_ + d];
    __nv_bfloat16 vh = __float2bfloat16(v);
    g_Vthi[idx] = vh;
    g_Vtlo[idx] = __float2bfloat16(v - __bfloat162float(vh));
}

__device__ __forceinline__ void split2(float x, float y, uint32_t &hi, uint32_t &lo) {
    __nv_bfloat162 h = __floats2bfloat162_rn(x, y);        // .x = x (low 16 bits)
    float hx = __bfloat162float(__low2bfloat16(h));
    float hy = __bfloat162float(__high2bfloat16(h));
    __nv_bfloat162 l = __floats2bfloat162_rn(x - hx, y - hy);
    hi = *reinterpret_cast<uint32_t*>(&h);
    lo = *reinterpret_cast<uint32_t*>(&l);
}

__device__ __forceinline__ void ldsm4(uint32_t addr, uint32_t &r0, uint32_t &r1,
                                      uint32_t &r2, uint32_t &r3) {
    asm volatile("ldmatrix.sync.aligned.m8n8.x4.shared.b16 {%0,%1,%2,%3}, [%4];"
                 : "=r"(r0), "=r"(r1), "=r"(r2), "=r"(r3) : "r"(addr));
}

__device__ __forceinline__ void mma_bf16(float c[4], const uint32_t a[4],
                                         uint32_t b0, uint32_t b1) {
    asm volatile("mma.sync.aligned.m16n8k16.row.col.f32.bf16.bf16.f32 "
                 "{%0,%1,%2,%3}, {%4,%5,%6,%7}, {%8,%9}, {%0,%1,%2,%3};"
                 : "+f"(c[0]), "+f"(c[1]), "+f"(c[2]), "+f"(c[3])
                 : "r"(a[0]), "r"(a[1]), "r"(a[2]), "r"(a[3]), "r"(b0), "r"(b1));
}

__global__ __launch_bounds__(NT) void attn_tc(
    const float* __restrict__ Q, float* __restrict__ Out, float* __restrict__ Attn)
{
    __shared__ __align__(16) __nv_bfloat16 sH[BK * KSTR];
    __shared__ __align__(16) __nv_bfloat16 sL[BK * KSTR];

    const int tid  = threadIdx.x;
    const int lane = tid & 31;
    const int w    = tid >> 5;
    const int b    = blockIdx.y;
    const int bx   = blockIdx.x;
    const int qt   = (bx & 1) ? (63 - (bx >> 1)) : (bx >> 1);   // work-pairing balance

    const int qr  = w * 16 + (lane >> 2);   // local q row (first of the +8 pair)
    const int qc2 = (lane & 3) * 2;         // fragment col pair base

    const float NEGINF = __int_as_float(0xff800000);

    // ---- zero-fill upper-triangle tiles of the attention output ----
    {
        const int zstart = (qt + 1) * BK;
        const int zw4 = (S_ - zstart) >> 2;
        if (zw4 > 0) {
            const float4 z4 = make_float4(0.f, 0.f, 0.f, 0.f);
            const int total = BQ * zw4;
            for (int i = tid; i < total; i += NT) {
                int r = i / zw4, c = i - r * zw4;
                ((float4*)&Attn[((size_t)(b * S_ + qt * BQ + r)) * S_ + zstart])[c] = z4;
            }
        }
    }

    const size_t qg0 = (size_t)(b * S_ + qt * BQ + qr);
    float* arow0 = Attn + qg0 * S_;
    float* arow1 = Attn + (qg0 + 8) * S_;

    // ---- Q fragments (loop-invariant), split into bf16 hi/lo ----
    uint32_t qh[4][4], ql[4][4];
    {
        const float* q0p = Q + qg0 * D_;
        const float* q1p = Q + (qg0 + 8) * D_;
        #pragma unroll
        for (int kb = 0; kb < 4; kb++) {
            float2 a0 = *(const float2*)&q0p[kb * 16 + qc2];
            float2 a1 = *(const float2*)&q1p[kb * 16 + qc2];
            float2 a2 = *(const float2*)&q0p[kb * 16 + 8 + qc2];
            float2 a3 = *(const float2*)&q1p[kb * 16 + 8 + qc2];
            split2(a0.x, a0.y, qh[kb][0], ql[kb][0]);
            split2(a1.x, a1.y, qh[kb][1], ql[kb][1]);
            split2(a2.x, a2.y, qh[kb][2], ql[kb][2]);
            split2(a3.x, a3.y, qh[kb][3], ql[kb][3]);
        }
    }

    // ---- ldmatrix lane base addresses ----
    uint32_t baseH = (uint32_t)__cvta_generic_to_shared(sH);
    uint32_t baseL = (uint32_t)__cvta_generic_to_shared(sL);
    {
        int lr    = lane & 7;
        int khalf = (lane >> 3) & 1;
        int nhalf = (lane >> 4) & 1;
        uint32_t off = (uint32_t)(((lr + nhalf * 8) * KSTR + khalf * 8) * 2);
        baseH += off; baseL += off;
    }

    float m0 = -1e30f, m1 = -1e30f, l0 = 0.f, l1 = 0.f;

    // =============================== PASS 1 ===============================
    for (int kt = 0; kt <= qt; kt++) {
        __syncthreads();
        {   // K tile: plain uint4 copies of pre-split bf16
            const uint4* srcH = (const uint4*)(g_Khi + ((size_t)(b * S_ + kt * BK)) * D_);
            const uint4* srcL = (const uint4*)(g_Klo + ((size_t)(b * S_ + kt * BK)) * D_);
            #pragma unroll
            for (int i = tid; i < 512; i += NT) {
                int r = i >> 3, c = i & 7;
                *(uint4*)&sH[r * KSTR + c * 8] = srcH[i];
                *(uint4*)&sL[r * KSTR + c * 8] = srcL[i];
            }
        }
        __syncthreads();

        float acc[8][4];
        #pragma unroll
        for (int nb = 0; nb < 8; nb++)
            #pragma unroll
            for (int j = 0; j < 4; j++) acc[nb][j] = 0.f;

        #pragma unroll
        for (int kb = 0; kb < 4; kb++) {
            #pragma unroll
            for (int np = 0; np < 4; np++) {
                uint32_t off = (uint32_t)((np * 16 * KSTR + kb * 16) * 2);
                uint32_t h0, h1, h2, h3, g0, g1, g2, g3;
                ldsm4(baseH + off, h0, h1, h2, h3);
                ldsm4(baseL + off, g0, g1, g2, g3);
                mma_bf16(acc[2*np],   qh[kb], h0, h1);
                mma_bf16(acc[2*np],   qh[kb], g0, g1);
                mma_bf16(acc[2*np],   ql[kb], h0, h1);
                mma_bf16(acc[2*np+1], qh[kb], h2, h3);
                mma_bf16(acc[2*np+1], qh[kb], g2, g3);
                mma_bf16(acc[2*np+1], ql[kb], h2, h3);
            }
        }

        // epilogue: scale, diagonal mask, online m/l, store raw scores
        float tm0 = -1e30f, tm1 = -1e30f;
        #pragma unroll
        for (int nb = 0; nb < 8; nb++) {
            acc[nb][0] *= 0.125f; acc[nb][1] *= 0.125f;
            acc[nb][2] *= 0.125f; acc[nb][3] *= 0.125f;
            if (kt == qt) {
                int cl = nb * 8 + qc2;
                if (cl     > qr)     acc[nb][0] = NEGINF;
                if (cl + 1 > qr)     acc[nb][1] = NEGINF;
                if (cl     > qr + 8) acc[nb][2] = NEGINF;
                if (cl + 1 > qr + 8) acc[nb][3] = NEGINF;
            }
            tm0 = fmaxf(tm0, fmaxf(acc[nb][0], acc[nb][1]));
            tm1 = fmaxf(tm1, fmaxf(acc[nb][2], acc[nb][3]));
        }
        const float nm0 = fmaxf(m0, tm0);
        const float nm1 = fmaxf(m1, tm1);
        float add0 = 0.f, add1 = 0.f;
        const int cb = kt * 64;
        #pragma unroll
        for (int nb = 0; nb < 8; nb++) {
            add0 += exp2f((acc[nb][0] - nm0) * L2E) + exp2f((acc[nb][1] - nm0) * L2E);
            add1 += exp2f((acc[nb][2] - nm1) * L2E) + exp2f((acc[nb][3] - nm1) * L2E);
            *(float2*)&arow0[cb + nb * 8 + qc2] = make_float2(acc[nb][0], acc[nb][1]);
            *(float2*)&arow1[cb + nb * 8 + qc2] = make_float2(acc[nb][2], acc[nb][3]);
        }
        l0 = l0 * exp2f((m0 - nm0) * L2E) + add0;  m0 = nm0;
        l1 = l1 * exp2f((m1 - nm1) * L2E) + add1;  m1 = nm1;
    }

    // reduce (m,l) across the 4 lanes sharing each row
    #pragma unroll
    for (int off = 1; off <= 2; off <<= 1) {
        float mo, lo_;
        mo  = __shfl_xor_sync(0xffffffffu, m0, off);
        lo_ = __shfl_xor_sync(0xffffffffu, l0, off);
        { float nm = fmaxf(m0, mo); l0 = l0 * exp2f((m0 - nm) * L2E) + lo_ * exp2f((mo - nm) * L2E); m0 = nm; }
        mo  = __shfl_xor_sync(0xffffffffu, m1, off);
        lo_ = __shfl_xor_sync(0xffffffffu, l1, off);
        { float nm = fmaxf(m1, mo); l1 = l1 * exp2f((m1 - nm) * L2E) + lo_ * exp2f((mo - nm) * L2E); m1 = nm; }
    }
    const float il0 = 1.0f / l0;
    const float il1 = 1.0f / l1;

    // =============================== PASS 2 ===============================
    float accO[8][4];
    #pragma unroll
    for (int nb = 0; nb < 8; nb++)
        #pragma unroll
        for (int j = 0; j < 4; j++) accO[nb][j] = 0.f;

    for (int kt = 0; kt <= qt; kt++) {
        __syncthreads();
        {   // V tile (pre-transposed [d][s]): plain uint4 copies
            #pragma unroll
            for (int i = tid; i < 512; i += NT) {
                int d = i >> 3, c = i & 7;
                size_t gi = ((size_t)(b * 64 + d)) * 512 + (size_t)kt * 8 + c;
                *(uint4*)&sH[d * KSTR + c * 8] = ((const uint4*)g_Vthi)[gi];
                *(uint4*)&sL[d * KSTR + c * 8] = ((const uint4*)g_Vtlo)[gi];
            }
        }

        // P fragments: re-read this thread's own raw scores, normalize, write back
        uint32_t ph[4][4], pl[4][4];
        const int cb = kt * 64;
        #pragma unroll
        for (int kb = 0; kb < 4; kb++) {
            #pragma unroll
            for (int h = 0; h < 2; h++) {
                int col = cb + kb * 16 + h * 8 + qc2;
                float2 s0 = *(float2*)&arow0[col];
                float2 s1 = *(float2*)&arow1[col];
                float p00 = exp2f((s0.x - m0) * L2E) * il0;
                float p01 = exp2f((s0.y - m0) * L2E) * il0;
                float p10 = exp2f((s1.x - m1) * L2E) * il1;
                float p11 = exp2f((s1.y - m1) * L2E) * il1;
                *(float2*)&arow0[col] = make_float2(p00, p01);
                *(float2*)&arow1[col] = make_float2(p10, p11);
                split2(p00, p01, ph[kb][h * 2 + 0], pl[kb][h * 2 + 0]);
                split2(p10, p11, ph[kb][h * 2 + 1], pl[kb][h * 2 + 1]);
            }
        }
        __syncthreads();

        #pragma unroll
        for (int kb = 0; kb < 4; kb++) {
            #pragma unroll
            for (int np = 0; np < 4; np++) {
                uint32_t off = (uint32_t)((np * 16 * KSTR + kb * 16) * 2);
                uint32_t h0, h1, h2, h3, g0, g1, g2, g3;
                ldsm4(baseH + off, h0, h1, h2, h3);
                ldsm4(baseL + off, g0, g1, g2, g3);
                mma_bf16(accO[2*np],   ph[kb], h0, h1);
                mma_bf16(accO[2*np],   ph[kb], g0, g1);
                mma_bf16(accO[2*np],   pl[kb], h0, h1);
                mma_bf16(accO[2*np+1], ph[kb], h2, h3);
                mma_bf16(accO[2*np+1], ph[kb], g2, g3);
                mma_bf16(accO[2*np+1], pl[kb], h2, h3);
            }
        }
    }

    // ---- write O ----
    {
        float* orow0 = Out + qg0 * D_;
        float* orow1 = Out + (qg0 + 8) * D_;
        #pragma unroll
        for (int nb = 0; nb < 8; nb++) {
            *(float2*)&orow0[nb * 8 + qc2] = make_float2(accO[nb][0], accO[nb][1]);
            *(float2*)&orow1[nb * 8 + qc2] = make_float2(accO[nb][2], accO[nb][3]);
        }
    }
}

extern "C" void kernel_launch(void* const* d_in, const int* in_sizes, int n_in,
                              void* d_out, int out_size) {
    (void)in_sizes; (void)n_in; (void)out_size;
    const float* Q = (const float*)d_in[0];
    const float* K = (const float*)d_in[1];
    const float* V = (const float*)d_in[2];
    float* Out  = (float*)d_out;
    float* Attn = Out + (size_t)B_ * S_ * D_;

    preconvert<<<(B_*S_*D_ + 255) / 256, 256>>>(K, V);
    dim3 grid(S_ / BQ, B_);
    attn_tc<<<grid, NT>>>(Q, Out, Attn);
}

// round 5
// speedup vs baseline: 2.0922x; 1.5821x over previous
#include <cuda_runtime.h>
#include <cuda_bf16.h>
#include <cstdint>

#define B_   8
#define S_   4096
#define D_   64
#define BQ   64
#define NT   128
#define L2E  1.4426950408889634f
#define TB   8192          // one 64x64 bf16 tile, swizzled, bytes
// smem layout (48 KB static, no opt-in attribute needed):
//   [0      .. 16384)  K stage 0 (KH, KL)
//   [16384  .. 32768)  K stage 1 (KH, KL)
//   [32768  .. 49152)  V buffer  (VH, VL)
#define KSTG   16384
#define VOFF   32768

// Pre-split operands (bf16 hi/lo) + per-row softmax stats.
__device__ __align__(16) __nv_bfloat16 g_Khi[B_*S_*D_];
__device__ __align__(16) __nv_bfloat16 g_Klo[B_*S_*D_];
__device__ __align__(16) __nv_bfloat16 g_Vthi[B_*D_*S_];   // V transposed: [b][d][s]
__device__ __align__(16) __nv_bfloat16 g_Vtlo[B_*D_*S_];
__device__ float g_m [B_*S_];
__device__ float g_il[B_*S_];

__global__ void preconvert(const float* __restrict__ K, const float* __restrict__ V) {
    int idx = blockIdx.x * blockDim.x + threadIdx.x;
    if (idx >= B_*S_*D_) return;
    float k = K[idx];
    __nv_bfloat16 kh = __float2bfloat16(k);
    g_Khi[idx] = kh;
    g_Klo[idx] = __float2bfloat16(k - __bfloat162float(kh));
    int b = idx >> 18;
    int rem = idx & ((1 << 18) - 1);
    int d = rem >> 12;
    int s = rem & (S_ - 1);
    float v = V[(size_t)b*S_*D_ + (size_t)s*D_ + d];
    __nv_bfloat16 vh = __float2bfloat16(v);
    g_Vthi[idx] = vh;
    g_Vtlo[idx] = __float2bfloat16(v - __bfloat162float(vh));
}

__device__ __forceinline__ void split2(float x, float y, uint32_t &hi, uint32_t &lo) {
    __nv_bfloat162 h = __floats2bfloat162_rn(x, y);
    float hx = __bfloat162float(__low2bfloat16(h));
    float hy = __bfloat162float(__high2bfloat16(h));
    __nv_bfloat162 l = __floats2bfloat162_rn(x - hx, y - hy);
    hi = *reinterpret_cast<uint32_t*>(&h);
    lo = *reinterpret_cast<uint32_t*>(&l);
}

__device__ __forceinline__ void ldsm4(uint32_t addr, uint32_t &r0, uint32_t &r1,
                                      uint32_t &r2, uint32_t &r3) {
    asm volatile("ldmatrix.sync.aligned.m8n8.x4.shared.b16 {%0,%1,%2,%3}, [%4];"
                 : "=r"(r0), "=r"(r1), "=r"(r2), "=r"(r3) : "r"(addr));
}

__device__ __forceinline__ void mma_bf16(float c[4], const uint32_t a[4],
                                         uint32_t b0, uint32_t b1) {
    asm volatile("mma.sync.aligned.m16n8k16.row.col.f32.bf16.bf16.f32 "
                 "{%0,%1,%2,%3}, {%4,%5,%6,%7}, {%8,%9}, {%0,%1,%2,%3};"
                 : "+f"(c[0]), "+f"(c[1]), "+f"(c[2]), "+f"(c[3])
                 : "r"(a[0]), "r"(a[1]), "r"(a[2]), "r"(a[3]), "r"(b0), "r"(b1));
}

#define CP16(dst, src) \
    asm volatile("cp.async.cg.shared.global [%0], [%1], 16;" :: "r"(dst), "l"(src))

__global__ __launch_bounds__(NT, 3) void attn_flash(
    const float* __restrict__ Q, float* __restrict__ Out, float* __restrict__ Attn)
{
    __shared__ __align__(16) char smem[49152];
    const uint32_t smem_u32 = (uint32_t)__cvta_generic_to_shared(smem);

    const int tid  = threadIdx.x;
    const int lane = tid & 31;
    const int w    = tid >> 5;
    const int b    = blockIdx.y;
    const int bx   = blockIdx.x;
    const int qt   = (bx & 1) ? (63 - (bx >> 1)) : (bx >> 1);

    const int qr  = w * 16 + (lane >> 2);
    const int qc2 = (lane & 3) * 2;
    const int lr    = lane & 7;
    const int khalf = (lane >> 3) & 1;
    const int nhalf = (lane >> 4) & 1;
    const uint32_t rowbyte = (uint32_t)((nhalf * 8 + lr) * 128);

    const float NEGINF = __int_as_float(0xff800000);

    const size_t qg0 = (size_t)(b * S_ + qt * BQ + qr);
    float* arow0 = Attn + qg0 * S_;
    float* arow1 = Attn + (qg0 + 8) * S_;

    // ---- Q fragments (loop-invariant), split into bf16 hi/lo ----
    uint32_t qh[4][4], ql[4][4];
    {
        const float* q0p = Q + qg0 * D_;
        const float* q1p = Q + (qg0 + 8) * D_;
        #pragma unroll
        for (int kb = 0; kb < 4; kb++) {
            float2 a0 = *(const float2*)&q0p[kb * 16 + qc2];
            float2 a1 = *(const float2*)&q1p[kb * 16 + qc2];
            float2 a2 = *(const float2*)&q0p[kb * 16 + 8 + qc2];
            float2 a3 = *(const float2*)&q1p[kb * 16 + 8 + qc2];
            split2(a0.x, a0.y, qh[kb][0], ql[kb][0]);
            split2(a1.x, a1.y, qh[kb][1], ql[kb][1]);
            split2(a2.x, a2.y, qh[kb][2], ql[kb][2]);
            split2(a3.x, a3.y, qh[kb][3], ql[kb][3]);
        }
    }

    // ---- async loaders (swizzled 64x64 bf16 tiles) ----
    auto load_K = [&](int kt_, int s_) {
        const char* kh = (const char*)g_Khi + (size_t)b * 524288 + (size_t)kt_ * TB;
        const char* kl = (const char*)g_Klo + (size_t)b * 524288 + (size_t)kt_ * TB;
        const uint32_t dstS = smem_u32 + (uint32_t)(s_ * KSTG);
        #pragma unroll
        for (int it = 0; it < 4; it++) {
            const int i = tid + it * NT;
            const int r = i >> 3, j = i & 7;
            const uint32_t d = (uint32_t)(r * 128 + ((j ^ (r & 7)) << 4));
            CP16(dstS + d,      kh + i * 16);
            CP16(dstS + TB + d, kl + i * 16);
        }
    };
    auto load_V = [&](int kt_) {
        const uint32_t dstS = smem_u32 + VOFF;
        #pragma unroll
        for (int it = 0; it < 4; it++) {
            const int i = tid + it * NT;
            const int r = i >> 3, j = i & 7;        // r = d index, j = key chunk
            const uint32_t d = (uint32_t)(r * 128 + ((j ^ (r & 7)) << 4));
            const size_t vci = (((size_t)(b * 64 + r)) * 512 + (size_t)kt_ * 8 + j) << 4;
            CP16(dstS + d,      (const char*)g_Vthi + vci);
            CP16(dstS + TB + d, (const char*)g_Vtlo + vci);
        }
    };

    float m0 = -1e30f, m1 = -1e30f, l0 = 0.f, l1 = 0.f;
    float accO[8][4];
    #pragma unroll
    for (int nb = 0; nb < 8; nb++)
        #pragma unroll
        for (int j = 0; j < 4; j++) accO[nb][j] = 0.f;

    // prologue: K stage 0 in flight
    load_K(0, 0);
    asm volatile("cp.async.commit_group;" ::: "memory");

    for (int kt = 0; kt <= qt; kt++) {
        const uint32_t curK = smem_u32 + (uint32_t)((kt & 1) * KSTG);
        asm volatile("cp.async.wait_group 0;" ::: "memory");   // K(kt) ready
        __syncthreads();                                        // + V buffer free
        load_V(kt);
        asm volatile("cp.async.commit_group;" ::: "memory");
        if (kt < qt) {
            load_K(kt + 1, (kt + 1) & 1);
            asm volatile("cp.async.commit_group;" ::: "memory");
        }

        // ---------------- QK^T ----------------
        float acc[8][4];
        #pragma unroll
        for (int nb = 0; nb < 8; nb++)
            #pragma unroll
            for (int j = 0; j < 4; j++) acc[nb][j] = 0.f;

        #pragma unroll
        for (int kb = 0; kb < 4; kb++) {
            const uint32_t cj = (uint32_t)((((kb << 1) | khalf) ^ lr) << 4);
            #pragma unroll
            for (int np = 0; np < 4; np++) {
                const uint32_t a = curK + rowbyte + (uint32_t)(np * 2048) + cj;
                uint32_t h0, h1, h2, h3, g0, g1, g2, g3;
                ldsm4(a,      h0, h1, h2, h3);
                ldsm4(a + TB, g0, g1, g2, g3);
                mma_bf16(acc[2*np],   qh[kb], h0, h1);
                mma_bf16(acc[2*np],   qh[kb], g0, g1);
                mma_bf16(acc[2*np],   ql[kb], h0, h1);
                mma_bf16(acc[2*np+1], qh[kb], h2, h3);
                mma_bf16(acc[2*np+1], qh[kb], g2, g3);
                mma_bf16(acc[2*np+1], ql[kb], h2, h3);
            }
        }

        // ---------------- epilogue: scale, mask, row-max (lane-synced) ----------------
        float tm0 = -1e30f, tm1 = -1e30f;
        #pragma unroll
        for (int nb = 0; nb < 8; nb++) {
            acc[nb][0] *= 0.125f; acc[nb][1] *= 0.125f;
            acc[nb][2] *= 0.125f; acc[nb][3] *= 0.125f;
            if (kt == qt) {
                int cl = nb * 8 + qc2;
                if (cl     > qr)     acc[nb][0] = NEGINF;
                if (cl + 1 > qr)     acc[nb][1] = NEGINF;
                if (cl     > qr + 8) acc[nb][2] = NEGINF;
                if (cl + 1 > qr + 8) acc[nb][3] = NEGINF;
            }
            tm0 = fmaxf(tm0, fmaxf(acc[nb][0], acc[nb][1]));
            tm1 = fmaxf(tm1, fmaxf(acc[nb][2], acc[nb][3]));
        }
        // row max must agree across the 4 lanes covering each row's k-slice
        tm0 = fmaxf(tm0, __shfl_xor_sync(0xffffffffu, tm0, 1));
        tm0 = fmaxf(tm0, __shfl_xor_sync(0xffffffffu, tm0, 2));
        tm1 = fmaxf(tm1, __shfl_xor_sync(0xffffffffu, tm1, 1));
        tm1 = fmaxf(tm1, __shfl_xor_sync(0xffffffffu, tm1, 2));
        const float nm0 = fmaxf(m0, tm0);
        const float nm1 = fmaxf(m1, tm1);
        const float f0 = exp2f((m0 - nm0) * L2E);
        const float f1 = exp2f((m1 - nm1) * L2E);
        #pragma unroll
        for (int nb = 0; nb < 8; nb++) {
            accO[nb][0] *= f0; accO[nb][1] *= f0;
            accO[nb][2] *= f1; accO[nb][3] *= f1;
        }

        // P = exp(s - m) in registers; store raw s; pack P into bf16 hi/lo A-fragments
        float add0 = 0.f, add1 = 0.f;
        uint32_t ph[4][4], pl[4][4];
        const int cb = kt * 64;
        #pragma unroll
        for (int nb = 0; nb < 8; nb++) {
            const float p0 = exp2f((acc[nb][0] - nm0) * L2E);
            const float p1 = exp2f((acc[nb][1] - nm0) * L2E);
            const float p2 = exp2f((acc[nb][2] - nm1) * L2E);
            const float p3 = exp2f((acc[nb][3] - nm1) * L2E);
            add0 += p0 + p1;  add1 += p2 + p3;
            *(float2*)&arow0[cb + nb * 8 + qc2] = make_float2(acc[nb][0], acc[nb][1]);
            *(float2*)&arow1[cb + nb * 8 + qc2] = make_float2(acc[nb][2], acc[nb][3]);
            const int kb = nb >> 1, h = nb & 1;
            split2(p0, p1, ph[kb][h * 2 + 0], pl[kb][h * 2 + 0]);
            split2(p2, p3, ph[kb][h * 2 + 1], pl[kb][h * 2 + 1]);
        }
        l0 = l0 * f0 + add0;  m0 = nm0;
        l1 = l1 * f1 + add1;  m1 = nm1;

        // ---------------- P @ V ----------------
        asm volatile("cp.async.wait_group 1;" ::: "memory");   // V(kt) ready; K(kt+1) may fly
        __syncthreads();
        #pragma unroll
        for (int kb = 0; kb < 4; kb++) {
            const uint32_t cj = (uint32_t)((((kb << 1) | khalf) ^ lr) << 4);
            #pragma unroll
            for (int np = 0; np < 4; np++) {
                const uint32_t a = smem_u32 + VOFF + rowbyte + (uint32_t)(np * 2048) + cj;
                uint32_t h0, h1, h2, h3, g0, g1, g2, g3;
                ldsm4(a,      h0, h1, h2, h3);
                ldsm4(a + TB, g0, g1, g2, g3);
                mma_bf16(accO[2*np],   ph[kb], h0, h1);
                mma_bf16(accO[2*np],   ph[kb], g0, g1);
                mma_bf16(accO[2*np],   pl[kb], h0, h1);
                mma_bf16(accO[2*np+1], ph[kb], h2, h3);
                mma_bf16(accO[2*np+1], ph[kb], g2, g3);
                mma_bf16(accO[2*np+1], pl[kb], h2, h3);
            }
        }
    }

    // final (m,l) merge across the 4 lanes per row
    #pragma unroll
    for (int off = 1; off <= 2; off <<= 1) {
        float mo, lo_;
        mo  = __shfl_xor_sync(0xffffffffu, m0, off);
        lo_ = __shfl_xor_sync(0xffffffffu, l0, off);
        { float nm = fmaxf(m0, mo); l0 = l0 * exp2f((m0 - nm) * L2E) + lo_ * exp2f((mo - nm) * L2E); m0 = nm; }
        mo  = __shfl_xor_sync(0xffffffffu, m1, off);
        lo_ = __shfl_xor_sync(0xffffffffu, l1, off);
        { float nm = fmaxf(m1, mo); l1 = l1 * exp2f((m1 - nm) * L2E) + lo_ * exp2f((mo - nm) * L2E); m1 = nm; }
    }
    const float il0 = 1.0f / l0;
    const float il1 = 1.0f / l1;

    if ((lane & 3) == 0) {
        g_m [qg0]     = m0;  g_il[qg0]     = il0;
        g_m [qg0 + 8] = m1;  g_il[qg0 + 8] = il1;
    }

    {
        float* orow0 = Out + qg0 * D_;
        float* orow1 = Out + (qg0 + 8) * D_;
        #pragma unroll
        for (int nb = 0; nb < 8; nb++) {
            *(float2*)&orow0[nb * 8 + qc2] = make_float2(accO[nb][0] * il0, accO[nb][1] * il0);
            *(float2*)&orow1[nb * 8 + qc2] = make_float2(accO[nb][2] * il1, accO[nb][3] * il1);
        }
    }
}

// Normalize lower triangle of Attn with final (m, 1/l); zero the upper triangle.
__global__ __launch_bounds__(256) void fixup(float* __restrict__ Attn) {
    __shared__ float sm[64], sil[64];
    const int b  = blockIdx.y;
    const int qt = blockIdx.x;
    const int tid = threadIdx.x;
    if (tid < 64) {
        sm [tid] = g_m [b * S_ + qt * 64 + tid];
        sil[tid] = g_il[b * S_ + qt * 64 + tid];
    }
    __syncthreads();
    const int limit4 = (qt + 1) * 16;
    const float4 z4 = make_float4(0.f, 0.f, 0.f, 0.f);
    for (int i = tid; i < 64 * 1024; i += 256) {
        const int r  = i >> 10;
        const int c4 = i & 1023;
        float4* p = (float4*)(Attn + ((size_t)(b * S_ + qt * 64 + r)) * S_) + c4;
        if (c4 < limit4) {
            const float m = sm[r], il = sil[r];
            float4 v = *p;
            v.x = exp2f((v.x - m) * L2E) * il;
            v.y = exp2f((v.y - m) * L2E) * il;
            v.z = exp2f((v.z - m) * L2E) * il;
            v.w = exp2f((v.w - m) * L2E) * il;
            *p = v;
        } else {
            *p = z4;
        }
    }
}

extern "C" void kernel_launch(void* const* d_in, const int* in_sizes, int n_in,
                              void* d_out, int out_size) {
    (void)in_sizes; (void)n_in; (void)out_size;
    const float* Q = (const float*)d_in[0];
    const float* K = (const float*)d_in[1];
    const float* V = (const float*)d_in[2];
    float* Out  = (float*)d_out;
    float* Attn = Out + (size_t)B_ * S_ * D_;

    preconvert<<<(B_*S_*D_ + 255) / 256, 256>>>(K, V);
    dim3 grid(S_ / BQ, B_);
    attn_flash<<<grid, NT>>>(Q, Out, Attn);
    fixup<<<dim3(S_ / 64, B_), 256>>>(Attn);
}